// round 11
// baseline (speedup 1.0000x reference)
#include <cuda_runtime.h>
#include <cuda_fp16.h>

#define NN 50000
#define EE 1600000
#define SCB 196          // ceil(NN/256) scan blocks
#define NB  444          // fused-kernel grid: exactly 3 blocks/SM, one wave
#define NTILES 3125      // NN/16

// ---- scratch ----
__device__ uint2  g_xp2[NN * 32];        // node projections fp16 [N,128]
__device__ float  g_as[NN * 4];
__device__ float  g_at[NN * 4];
__device__ uint2  g_aeh[EE];             // per-edge a_e, 4 halfs
__device__ uint4  g_rec[EE];             // CSR: {w01h2, w23h2, src, pad}
__device__ int    g_deg[NN];             // zero-init first run; re-zeroed by k_scan
__device__ int    g_off[NN + 1];
__device__ int    g_cur[NN];
__device__ int    g_agg[SCB];
__device__ int    g_flag[SCB];           // zeroed by k_node block 0 each run

__device__ __forceinline__ unsigned long long pack2f(float a, float b) {
    unsigned long long r;
    asm("mov.b64 %0, {%1, %2};" : "=l"(r) : "f"(a), "f"(b));
    return r;
}
__device__ __forceinline__ void unpack2f(unsigned long long v, float& a, float& b) {
    asm("mov.b64 {%0, %1}, %2;" : "=f"(a), "=f"(b) : "l"(v));
}
__device__ __forceinline__ unsigned long long fma2f(unsigned long long a,
                                                    unsigned long long b,
                                                    unsigned long long c) {
    unsigned long long r;
    asm("fma.rn.f32x2 %0, %1, %2, %3;" : "=l"(r) : "l"(a), "l"(b), "l"(c));
    return r;
}

// ---------------------------------------------------------------
// K1: phase-staggered fused kernel, ONE wave of 444 blocks.
//     Each block owns 1/444 of GEMM tiles and 1/444 of edges.
//     bid < NB/2: GEMM phase then edge phase; else reversed.
//     => at any instant ~half the chip does FFMA (GEMM), half streams
//     edge_attr (DRAM) — true compute/memory overlap.
__global__ __launch_bounds__(256) void k_node(
    const float* __restrict__ x, const int* __restrict__ ei,
    const float* __restrict__ ea,
    const float* __restrict__ W_lin, const float* __restrict__ W_res,
    const float* __restrict__ bias,
    const float* __restrict__ w_s, const float* __restrict__ b_s,
    const float* __restrict__ w_t, const float* __restrict__ b_t,
    const float* __restrict__ W_edge, const float* __restrict__ w_e,
    float* __restrict__ out) {
    int t = threadIdx.x;
    __shared__ float sve[64];
    __shared__ float sx[16 * 64];
    __shared__ float sxp[16 * 132];
    __shared__ float sws[32], swt[32];

    // ---- setup: fold v_e, stage attn vectors, zero scan flags ----
    if (t < 64) {
        int h = t >> 4, k = t & 15;
        float s = 0.f;
#pragma unroll
        for (int f = 0; f < 32; f++) s += w_e[f] * W_edge[(h * 32 + f) * 16 + k];
        sve[t] = s;
    } else if (t < 96) {
        sws[t - 64] = w_s[t - 64];
    } else if (t < 128) {
        swt[t - 96] = w_t[t - 96];
    }
    if (blockIdx.x == 0 && t < SCB) g_flag[t] = 0;
    __syncthreads();

    // ---- edge phase: degree histogram + a_e dot -> fp16 ----
    auto edge_phase = [&]() {
        for (int e = blockIdx.x * 256 + t; e < EE; e += NB * 256) {
            int dst = ei[EE + e];
            atomicAdd(&g_deg[dst], 1);
            const float4* p = (const float4*)ea + e * 4;
            float av[16];
#pragma unroll
            for (int i = 0; i < 4; i++) {
                float4 q = p[i];
                av[4 * i] = q.x; av[4 * i + 1] = q.y;
                av[4 * i + 2] = q.z; av[4 * i + 3] = q.w;
            }
            float r[4];
#pragma unroll
            for (int h = 0; h < 4; h++) {
                const float* vv = sve + h * 16;
                float s = 0.f;
#pragma unroll
                for (int k = 0; k < 16; k++) s += vv[k] * av[k];
                r[h] = s;
            }
            half2 r01 = __floats2half2_rn(r[0], r[1]);
            half2 r23 = __floats2half2_rn(r[2], r[3]);
            uint2 u;
            u.x = *(unsigned*)&r01;
            u.y = *(unsigned*)&r23;
            g_aeh[e] = u;
        }
    };

    // ---- GEMM phase: node projections + a_s/a_t ----
    auto gemm_phase = [&]() {
        unsigned long long w2[32];
        {
            const float4* Wrow = (t < 128) ? ((const float4*)W_lin + t * 16)
                                           : ((const float4*)W_res + (t - 128) * 16);
#pragma unroll
            for (int k = 0; k < 16; k++) {
                float4 v = Wrow[k];
                w2[2 * k]     = pack2f(v.x, v.y);
                w2[2 * k + 1] = pack2f(v.z, v.w);
            }
        }
        float bval = (t >= 128) ? bias[t - 128] : 0.f;
        float bsv = b_s[0], btv = b_t[0];
        int th = t >> 5, tf = t & 31;

        for (int tile = blockIdx.x; tile < NTILES; tile += NB) {
            int n0 = tile * 16;
            __syncthreads();
            ((float4*)sx)[(t >> 4) * 16 + (t & 15)] =
                ((const float4*)x)[(n0 + (t >> 4)) * 16 + (t & 15)];
            __syncthreads();
#pragma unroll 1
            for (int i = 0; i < 16; i++) {
                const ulonglong2* xr = (const ulonglong2*)(sx + i * 64);
                unsigned long long a0 = 0ull, a1 = 0ull;
#pragma unroll
                for (int k = 0; k < 16; k++) {
                    ulonglong2 xv = xr[k];
                    a0 = fma2f(w2[2 * k],     xv.x, a0);
                    a1 = fma2f(w2[2 * k + 1], xv.y, a1);
                }
                float l0, h0, l1, h1;
                unpack2f(a0, l0, h0);
                unpack2f(a1, l1, h1);
                float acc = (l0 + l1) + (h0 + h1);
                if (t < 128) {
                    sxp[i * 132 + th * 33 + tf] = acc;
                    ((__half*)g_xp2)[(n0 + i) * 128 + t] = __float2half(acc);
                } else {
                    out[(n0 + i) * 128 + (t - 128)] = acc + bval;
                }
            }
            __syncthreads();
            if (t < 128) {
                int i = t >> 3, task = t & 7, h = task & 3;
                const float* wv  = (task < 4) ? sws : swt;
                const float* xpr = sxp + i * 132 + h * 33;
                float s = 0.f;
#pragma unroll
                for (int f = 0; f < 32; f++) s += xpr[f] * wv[f];
                if (task < 4) g_as[(n0 + i) * 4 + h] = s + bsv;
                else          g_at[(n0 + i) * 4 + h] = s + btv;
            }
        }
    };

    if (blockIdx.x < NB / 2) { gemm_phase(); edge_phase(); }
    else                     { edge_phase(); gemm_phase(); }
}

// ---------------------------------------------------------------
// K2: single-launch decoupled scan (196 co-resident blocks).
__global__ __launch_bounds__(256) void k_scan() {
    __shared__ int swsum[8];
    __shared__ int sbase[8];
    int t = threadIdx.x, lane = t & 31, w = t >> 5;
    int idx = blockIdx.x * 256 + t;
    int d = (idx < NN) ? g_deg[idx] : 0;

    int v = d;
#pragma unroll
    for (int o = 1; o < 32; o <<= 1) {
        int u = __shfl_up_sync(0xffffffffu, v, o);
        if (lane >= o) v += u;
    }
    if (lane == 31) swsum[w] = v;
    __syncthreads();
    if (w == 0) {
        int ws = (lane < 8) ? swsum[lane] : 0;
#pragma unroll
        for (int o = 1; o < 8; o <<= 1) {
            int u = __shfl_up_sync(0xffffffffu, ws, o);
            if (lane >= o) ws += u;
        }
        if (lane < 8) swsum[lane] = ws;
    }
    __syncthreads();
    int incl = v + (w > 0 ? swsum[w - 1] : 0);
    int total = swsum[7];

    if (t == 0) {
        g_agg[blockIdx.x] = total;
        __threadfence();
        g_flag[blockIdx.x] = 1;
    }

    int pre = 0;
    if (t < blockIdx.x) {
        while (((volatile int*)g_flag)[t] == 0) {}
        pre = ((volatile int*)g_agg)[t];
    }
#pragma unroll
    for (int o = 16; o > 0; o >>= 1) pre += __shfl_down_sync(0xffffffffu, pre, o);
    if (lane == 0) sbase[w] = pre;
    __syncthreads();
    if (t == 0) {
        int b = 0;
#pragma unroll
        for (int i = 0; i < 8; i++) b += sbase[i];
        sbase[0] = b;
    }
    __syncthreads();
    int base = sbase[0];

    if (idx < NN) {
        int off = base + incl - d;
        g_off[idx] = off;
        g_cur[idx] = off;
        g_deg[idx] = 0;
        if (idx == NN - 1) g_off[NN] = off + d;
    }
}

// ---------------------------------------------------------------
// K3: LEAN scatter — precomputed fp16 a_e, 8 coalesced streams/thread.
__global__ __launch_bounds__(256) void k_scatter(
    const int* __restrict__ ei, const float* __restrict__ b_e) {
    const int OC = EE / 8;
    int gid = blockIdx.x * blockDim.x + threadIdx.x;
    if (gid >= OC) return;
    float bev = b_e[0];

    int   e[8], src[8], dst[8];
    uint2 ae[8];
    float4 as4[8], at4[8];
#pragma unroll
    for (int k = 0; k < 8; k++) e[k] = gid + k * OC;
#pragma unroll
    for (int k = 0; k < 8; k++) { src[k] = ei[e[k]]; dst[k] = ei[EE + e[k]]; }
#pragma unroll
    for (int k = 0; k < 8; k++) ae[k] = g_aeh[e[k]];
#pragma unroll
    for (int k = 0; k < 8; k++) {
        as4[k] = ((const float4*)g_as)[src[k]];
        at4[k] = ((const float4*)g_at)[dst[k]];
    }
#pragma unroll
    for (int k = 0; k < 8; k++) {
        float2 a01 = __half22float2(*(half2*)&ae[k].x);
        float2 a23 = __half22float2(*(half2*)&ae[k].y);
        float al[4];
        al[0] = a01.x + as4[k].x + at4[k].x + bev;
        al[1] = a01.y + as4[k].y + at4[k].y + bev;
        al[2] = a23.x + as4[k].z + at4[k].z + bev;
        al[3] = a23.y + as4[k].w + at4[k].w + bev;
        float w[4];
#pragma unroll
        for (int h = 0; h < 4; h++) {
            float s = (al[h] >= 0.f) ? al[h] : 0.2f * al[h];
            w[h] = __expf(s);
        }
        int pos = atomicAdd(&g_cur[dst[k]], 1);
        half2 w01 = __floats2half2_rn(w[0], w[1]);
        half2 w23 = __floats2half2_rn(w[2], w[3]);
        uint4 rec;
        rec.x = *(unsigned*)&w01;
        rec.y = *(unsigned*)&w23;
        rec.z = (unsigned)src[k];
        rec.w = 0u;
        g_rec[pos] = rec;
    }
}

// ---------------------------------------------------------------
// K4: EDGE-PAIRED aggregation, batch-8 (unchanged from r10).
__device__ __forceinline__ void aggr_step(float* acc, float& sw,
                                          const uint4& r, const uint4& xv,
                                          int head) {
    unsigned wp = (head & 2) ? r.y : r.x;
    half2 hw = *(half2*)&wp;
    float w = (head & 1) ? __high2float(hw) : __low2float(hw);
    sw += w;
    float2 f0 = __half22float2(*(const half2*)&xv.x);
    float2 f1 = __half22float2(*(const half2*)&xv.y);
    float2 f2 = __half22float2(*(const half2*)&xv.z);
    float2 f3 = __half22float2(*(const half2*)&xv.w);
    acc[0] += w * f0.x; acc[1] += w * f0.y;
    acc[2] += w * f1.x; acc[3] += w * f1.y;
    acc[4] += w * f2.x; acc[5] += w * f2.y;
    acc[6] += w * f3.x; acc[7] += w * f3.y;
}

__global__ __launch_bounds__(256) void k_aggr(float* __restrict__ out) {
    int wid = (blockIdx.x * blockDim.x + threadIdx.x) >> 5;
    if (wid >= NN) return;
    int lane = threadIdx.x & 31;
    int half = lane >> 4;
    int sub  = lane & 15;
    int head = sub >> 2;
    int beg = g_off[wid], end = g_off[wid + 1];
    const uint4* xp4 = (const uint4*)g_xp2;

    float acc[8];
#pragma unroll
    for (int i = 0; i < 8; i++) acc[i] = 0.f;
    float sw = 0.f;

    int p = beg;
    for (; p + 8 <= end; p += 8) {
        uint4 r[4], xv[4];
#pragma unroll
        for (int j = 0; j < 4; j++) r[j] = g_rec[p + 2 * j + half];
#pragma unroll
        for (int j = 0; j < 4; j++) xv[j] = xp4[r[j].z * 16 + sub];
#pragma unroll
        for (int j = 0; j < 4; j++) aggr_step(acc, sw, r[j], xv[j], head);
    }
    for (; p + 2 <= end; p += 2) {
        uint4 r = g_rec[p + half];
        uint4 xv = xp4[r.z * 16 + sub];
        aggr_step(acc, sw, r, xv, head);
    }
    if (p < end) {
        uint4 r = g_rec[p];
        uint4 xv = xp4[r.z * 16 + sub];
        unsigned wp = (head & 2) ? r.y : r.x;
        half2 hw = *(half2*)&wp;
        float w = (head & 1) ? __high2float(hw) : __low2float(hw);
        if (half) w = 0.f;
        sw += w;
        float2 f0 = __half22float2(*(const half2*)&xv.x);
        float2 f1 = __half22float2(*(const half2*)&xv.y);
        float2 f2 = __half22float2(*(const half2*)&xv.z);
        float2 f3 = __half22float2(*(const half2*)&xv.w);
        acc[0] += w * f0.x; acc[1] += w * f0.y;
        acc[2] += w * f1.x; acc[3] += w * f1.y;
        acc[4] += w * f2.x; acc[5] += w * f2.y;
        acc[6] += w * f3.x; acc[7] += w * f3.y;
    }

    sw += __shfl_xor_sync(0xffffffffu, sw, 16);
#pragma unroll
    for (int i = 0; i < 8; i++)
        acc[i] += __shfl_xor_sync(0xffffffffu, acc[i], 16);

    float inv = (sw > 0.f) ? (1.f / sw) : 0.f;
    float4* o4 = (float4*)(out + wid * 128 + sub * 8 + half * 4);
    float4 ov = *o4;
    int b = half * 4;
    ov.x += inv * acc[b + 0]; ov.y += inv * acc[b + 1];
    ov.z += inv * acc[b + 2]; ov.w += inv * acc[b + 3];
    *o4 = ov;
}

// ---------------------------------------------------------------
extern "C" void kernel_launch(void* const* d_in, const int* in_sizes, int n_in,
                              void* d_out, int out_size) {
    const float* x      = (const float*)d_in[0];
    const int*   ei     = (const int*)  d_in[1];
    const float* ea     = (const float*)d_in[2];
    const float* W_lin  = (const float*)d_in[3];
    const float* w_s    = (const float*)d_in[4];
    const float* b_s    = (const float*)d_in[5];
    const float* w_t    = (const float*)d_in[6];
    const float* b_t    = (const float*)d_in[7];
    const float* W_edge = (const float*)d_in[8];
    const float* w_e    = (const float*)d_in[9];
    const float* b_e    = (const float*)d_in[10];
    const float* W_res  = (const float*)d_in[11];
    const float* bias   = (const float*)d_in[12];
    float* out = (float*)d_out;

    k_node<<<NB, 256>>>(x, ei, ea, W_lin, W_res, bias,
                        w_s, b_s, w_t, b_t, W_edge, w_e, out);
    k_scan<<<SCB, 256>>>();
    k_scatter<<<(EE / 8 + 255) / 256, 256>>>(ei, b_e);
    k_aggr<<<(NN * 32) / 256, 256>>>(out);
}

// round 12
// speedup vs baseline: 1.0104x; 1.0104x over previous
#include <cuda_runtime.h>
#include <cuda_fp16.h>

#define NN 50000
#define EE 1600000
#define SCB 196          // ceil(NN/256) scan blocks
#define NODE_BLKS 600
#define DEG_BLKS  1024

// ---- scratch ----
__device__ uint2  g_xp2[NN * 32];        // node projections fp16 [N,128]
__device__ float  g_as[NN * 4];
__device__ float  g_at[NN * 4];
__device__ uint2  g_aeh[EE];             // per-edge a_e, 4 halfs
__device__ unsigned short g_rank[EE];    // edge rank within its dst
__device__ uint4  g_rec[EE];             // CSR: {w01h2, w23h2, src, pad}
__device__ int    g_deg[NN];             // zero-init first run; re-zeroed by k_scan
__device__ int    g_off[NN + 1];
__device__ int    g_agg[SCB];
__device__ int    g_flag[SCB];           // zeroed by k_pre each run

__device__ __forceinline__ unsigned long long pack2f(float a, float b) {
    unsigned long long r;
    asm("mov.b64 %0, {%1, %2};" : "=l"(r) : "f"(a), "f"(b));
    return r;
}
__device__ __forceinline__ void unpack2f(unsigned long long v, float& a, float& b) {
    asm("mov.b64 {%0, %1}, %2;" : "=f"(a), "=f"(b) : "l"(v));
}
__device__ __forceinline__ unsigned long long fma2f(unsigned long long a,
                                                    unsigned long long b,
                                                    unsigned long long c) {
    unsigned long long r;
    asm("fma.rn.f32x2 %0, %1, %2, %3;" : "=l"(r) : "l"(a), "l"(b), "l"(c));
    return r;
}

// ---------------------------------------------------------------
// K0: zero scan flags (tiny; also shifts profile slot so k_scatter is #4)
__global__ void k_pre() {
    if (threadIdx.x < SCB) g_flag[threadIdx.x] = 0;
}

// ---------------------------------------------------------------
// K1: FUSED (r10 structure). blocks < NODE_BLKS: persistent GEMM.
//     Remaining blocks: edge pass — degree histogram KEEPING the rank,
//     + a_e dot -> fp16.
__global__ __launch_bounds__(256) void k_node(
    const float* __restrict__ x, const int* __restrict__ ei,
    const float* __restrict__ ea,
    const float* __restrict__ W_lin, const float* __restrict__ W_res,
    const float* __restrict__ bias,
    const float* __restrict__ w_s, const float* __restrict__ b_s,
    const float* __restrict__ w_t, const float* __restrict__ b_t,
    const float* __restrict__ W_edge, const float* __restrict__ w_e,
    float* __restrict__ out) {
    int t = threadIdx.x;
    if (blockIdx.x >= NODE_BLKS) {
        // ---- edge pass ----
        __shared__ float sve[64];
        if (t < 64) {
            int h = t >> 4, k = t & 15;
            float s = 0.f;
#pragma unroll
            for (int f = 0; f < 32; f++) s += w_e[f] * W_edge[(h * 32 + f) * 16 + k];
            sve[t] = s;
        }
        __syncthreads();
        int nb = gridDim.x - NODE_BLKS;
        for (int e = (blockIdx.x - NODE_BLKS) * 256 + t; e < EE;
             e += nb * 256) {
            int dst = ei[EE + e];
            int rk = atomicAdd(&g_deg[dst], 1);
            g_rank[e] = (unsigned short)rk;
            const float4* p = (const float4*)ea + e * 4;
            float av[16];
#pragma unroll
            for (int i = 0; i < 4; i++) {
                float4 q = p[i];
                av[4 * i] = q.x; av[4 * i + 1] = q.y;
                av[4 * i + 2] = q.z; av[4 * i + 3] = q.w;
            }
            float r[4];
#pragma unroll
            for (int h = 0; h < 4; h++) {
                const float* vv = sve + h * 16;
                float s = 0.f;
#pragma unroll
                for (int k = 0; k < 16; k++) s += vv[k] * av[k];
                r[h] = s;
            }
            half2 r01 = __floats2half2_rn(r[0], r[1]);
            half2 r23 = __floats2half2_rn(r[2], r[3]);
            uint2 u;
            u.x = *(unsigned*)&r01;
            u.y = *(unsigned*)&r23;
            g_aeh[e] = u;
        }
        return;
    }
    // ---- GEMM path ----
    __shared__ float sx[16 * 64];
    __shared__ float sxp[16 * 132];
    __shared__ float sws[32], swt[32];

    unsigned long long w2[32];
    {
        const float4* Wrow = (t < 128) ? ((const float4*)W_lin + t * 16)
                                       : ((const float4*)W_res + (t - 128) * 16);
#pragma unroll
        for (int k = 0; k < 16; k++) {
            float4 v = Wrow[k];
            w2[2 * k]     = pack2f(v.x, v.y);
            w2[2 * k + 1] = pack2f(v.z, v.w);
        }
    }
    float bval = (t >= 128) ? bias[t - 128] : 0.f;
    if (t < 32) sws[t] = w_s[t];
    else if (t < 64) swt[t - 32] = w_t[t - 32];
    float bsv = b_s[0], btv = b_t[0];
    int th = t >> 5, tf = t & 31;

    for (int tile = blockIdx.x; tile < NN / 16; tile += NODE_BLKS) {
        int n0 = tile * 16;
        __syncthreads();
        ((float4*)sx)[(t >> 4) * 16 + (t & 15)] =
            ((const float4*)x)[(n0 + (t >> 4)) * 16 + (t & 15)];
        __syncthreads();
#pragma unroll 1
        for (int i = 0; i < 16; i++) {
            const ulonglong2* xr = (const ulonglong2*)(sx + i * 64);
            unsigned long long a0 = 0ull, a1 = 0ull;
#pragma unroll
            for (int k = 0; k < 16; k++) {
                ulonglong2 xv = xr[k];
                a0 = fma2f(w2[2 * k],     xv.x, a0);
                a1 = fma2f(w2[2 * k + 1], xv.y, a1);
            }
            float l0, h0, l1, h1;
            unpack2f(a0, l0, h0);
            unpack2f(a1, l1, h1);
            float acc = (l0 + l1) + (h0 + h1);
            if (t < 128) {
                sxp[i * 132 + th * 33 + tf] = acc;
                ((__half*)g_xp2)[(n0 + i) * 128 + t] = __float2half(acc);
            } else {
                out[(n0 + i) * 128 + (t - 128)] = acc + bval;
            }
        }
        __syncthreads();
        if (t < 128) {
            int i = t >> 3, task = t & 7, h = task & 3;
            const float* wv  = (task < 4) ? sws : swt;
            const float* xpr = sxp + i * 132 + h * 33;
            float s = 0.f;
#pragma unroll
            for (int f = 0; f < 32; f++) s += xpr[f] * wv[f];
            if (task < 4) g_as[(n0 + i) * 4 + h] = s + bsv;
            else          g_at[(n0 + i) * 4 + h] = s + btv;
        }
    }
}

// ---------------------------------------------------------------
// K2: single-launch decoupled scan (196 co-resident blocks).
__global__ __launch_bounds__(256) void k_scan() {
    __shared__ int swsum[8];
    __shared__ int sbase[8];
    int t = threadIdx.x, lane = t & 31, w = t >> 5;
    int idx = blockIdx.x * 256 + t;
    int d = (idx < NN) ? g_deg[idx] : 0;

    int v = d;
#pragma unroll
    for (int o = 1; o < 32; o <<= 1) {
        int u = __shfl_up_sync(0xffffffffu, v, o);
        if (lane >= o) v += u;
    }
    if (lane == 31) swsum[w] = v;
    __syncthreads();
    if (w == 0) {
        int ws = (lane < 8) ? swsum[lane] : 0;
#pragma unroll
        for (int o = 1; o < 8; o <<= 1) {
            int u = __shfl_up_sync(0xffffffffu, ws, o);
            if (lane >= o) ws += u;
        }
        if (lane < 8) swsum[lane] = ws;
    }
    __syncthreads();
    int incl = v + (w > 0 ? swsum[w - 1] : 0);
    int total = swsum[7];

    if (t == 0) {
        g_agg[blockIdx.x] = total;
        __threadfence();
        g_flag[blockIdx.x] = 1;
    }

    int pre = 0;
    if (t < blockIdx.x) {
        while (((volatile int*)g_flag)[t] == 0) {}
        pre = ((volatile int*)g_agg)[t];
    }
#pragma unroll
    for (int o = 16; o > 0; o >>= 1) pre += __shfl_down_sync(0xffffffffu, pre, o);
    if (lane == 0) sbase[w] = pre;
    __syncthreads();
    if (t == 0) {
        int b = 0;
#pragma unroll
        for (int i = 0; i < 8; i++) b += sbase[i];
        sbase[0] = b;
    }
    __syncthreads();
    int base = sbase[0];

    if (idx < NN) {
        int off = base + incl - d;
        g_off[idx] = off;
        g_deg[idx] = 0;
        if (idx == NN - 1) g_off[NN] = off + d;
    }
}

// ---------------------------------------------------------------
// K3: ATOMIC-FREE scatter — pos = g_off[dst] + precomputed rank.
//     8 coalesced streams/thread. (Profiled slot #4.)
__global__ __launch_bounds__(256) void k_scatter(
    const int* __restrict__ ei, const float* __restrict__ b_e) {
    const int OC = EE / 8;
    int gid = blockIdx.x * blockDim.x + threadIdx.x;
    if (gid >= OC) return;
    float bev = b_e[0];

    int   e[8], src[8], dst[8], rk[8];
    uint2 ae[8];
    float4 as4[8], at4[8];
#pragma unroll
    for (int k = 0; k < 8; k++) e[k] = gid + k * OC;
#pragma unroll
    for (int k = 0; k < 8; k++) { src[k] = ei[e[k]]; dst[k] = ei[EE + e[k]]; }
#pragma unroll
    for (int k = 0; k < 8; k++) rk[k] = g_rank[e[k]];
#pragma unroll
    for (int k = 0; k < 8; k++) ae[k] = g_aeh[e[k]];
#pragma unroll
    for (int k = 0; k < 8; k++) {
        as4[k] = ((const float4*)g_as)[src[k]];
        at4[k] = ((const float4*)g_at)[dst[k]];
    }
    int pos[8];
#pragma unroll
    for (int k = 0; k < 8; k++) pos[k] = g_off[dst[k]] + rk[k];
#pragma unroll
    for (int k = 0; k < 8; k++) {
        float2 a01 = __half22float2(*(half2*)&ae[k].x);
        float2 a23 = __half22float2(*(half2*)&ae[k].y);
        float al[4];
        al[0] = a01.x + as4[k].x + at4[k].x + bev;
        al[1] = a01.y + as4[k].y + at4[k].y + bev;
        al[2] = a23.x + as4[k].z + at4[k].z + bev;
        al[3] = a23.y + as4[k].w + at4[k].w + bev;
        float w[4];
#pragma unroll
        for (int h = 0; h < 4; h++) {
            float s = (al[h] >= 0.f) ? al[h] : 0.2f * al[h];
            w[h] = __expf(s);
        }
        half2 w01 = __floats2half2_rn(w[0], w[1]);
        half2 w23 = __floats2half2_rn(w[2], w[3]);
        uint4 rec;
        rec.x = *(unsigned*)&w01;
        rec.y = *(unsigned*)&w23;
        rec.z = (unsigned)src[k];
        rec.w = 0u;
        g_rec[pos[k]] = rec;
    }
}

// ---------------------------------------------------------------
// K4: EDGE-PAIRED aggregation, batch-8 (unchanged from r10).
__device__ __forceinline__ void aggr_step(float* acc, float& sw,
                                          const uint4& r, const uint4& xv,
                                          int head) {
    unsigned wp = (head & 2) ? r.y : r.x;
    half2 hw = *(half2*)&wp;
    float w = (head & 1) ? __high2float(hw) : __low2float(hw);
    sw += w;
    float2 f0 = __half22float2(*(const half2*)&xv.x);
    float2 f1 = __half22float2(*(const half2*)&xv.y);
    float2 f2 = __half22float2(*(const half2*)&xv.z);
    float2 f3 = __half22float2(*(const half2*)&xv.w);
    acc[0] += w * f0.x; acc[1] += w * f0.y;
    acc[2] += w * f1.x; acc[3] += w * f1.y;
    acc[4] += w * f2.x; acc[5] += w * f2.y;
    acc[6] += w * f3.x; acc[7] += w * f3.y;
}

__global__ __launch_bounds__(256) void k_aggr(float* __restrict__ out) {
    int wid = (blockIdx.x * blockDim.x + threadIdx.x) >> 5;
    if (wid >= NN) return;
    int lane = threadIdx.x & 31;
    int half = lane >> 4;
    int sub  = lane & 15;
    int head = sub >> 2;
    int beg = g_off[wid], end = g_off[wid + 1];
    const uint4* xp4 = (const uint4*)g_xp2;

    float acc[8];
#pragma unroll
    for (int i = 0; i < 8; i++) acc[i] = 0.f;
    float sw = 0.f;

    int p = beg;
    for (; p + 8 <= end; p += 8) {
        uint4 r[4], xv[4];
#pragma unroll
        for (int j = 0; j < 4; j++) r[j] = g_rec[p + 2 * j + half];
#pragma unroll
        for (int j = 0; j < 4; j++) xv[j] = xp4[r[j].z * 16 + sub];
#pragma unroll
        for (int j = 0; j < 4; j++) aggr_step(acc, sw, r[j], xv[j], head);
    }
    for (; p + 2 <= end; p += 2) {
        uint4 r = g_rec[p + half];
        uint4 xv = xp4[r.z * 16 + sub];
        aggr_step(acc, sw, r, xv, head);
    }
    if (p < end) {
        uint4 r = g_rec[p];
        uint4 xv = xp4[r.z * 16 + sub];
        unsigned wp = (head & 2) ? r.y : r.x;
        half2 hw = *(half2*)&wp;
        float w = (head & 1) ? __high2float(hw) : __low2float(hw);
        if (half) w = 0.f;
        sw += w;
        float2 f0 = __half22float2(*(const half2*)&xv.x);
        float2 f1 = __half22float2(*(const half2*)&xv.y);
        float2 f2 = __half22float2(*(const half2*)&xv.z);
        float2 f3 = __half22float2(*(const half2*)&xv.w);
        acc[0] += w * f0.x; acc[1] += w * f0.y;
        acc[2] += w * f1.x; acc[3] += w * f1.y;
        acc[4] += w * f2.x; acc[5] += w * f2.y;
        acc[6] += w * f3.x; acc[7] += w * f3.y;
    }

    sw += __shfl_xor_sync(0xffffffffu, sw, 16);
#pragma unroll
    for (int i = 0; i < 8; i++)
        acc[i] += __shfl_xor_sync(0xffffffffu, acc[i], 16);

    float inv = (sw > 0.f) ? (1.f / sw) : 0.f;
    float4* o4 = (float4*)(out + wid * 128 + sub * 8 + half * 4);
    float4 ov = *o4;
    int b = half * 4;
    ov.x += inv * acc[b + 0]; ov.y += inv * acc[b + 1];
    ov.z += inv * acc[b + 2]; ov.w += inv * acc[b + 3];
    *o4 = ov;
}

// ---------------------------------------------------------------
extern "C" void kernel_launch(void* const* d_in, const int* in_sizes, int n_in,
                              void* d_out, int out_size) {
    const float* x      = (const float*)d_in[0];
    const int*   ei     = (const int*)  d_in[1];
    const float* ea     = (const float*)d_in[2];
    const float* W_lin  = (const float*)d_in[3];
    const float* w_s    = (const float*)d_in[4];
    const float* b_s    = (const float*)d_in[5];
    const float* w_t    = (const float*)d_in[6];
    const float* b_t    = (const float*)d_in[7];
    const float* W_edge = (const float*)d_in[8];
    const float* w_e    = (const float*)d_in[9];
    const float* b_e    = (const float*)d_in[10];
    const float* W_res  = (const float*)d_in[11];
    const float* bias   = (const float*)d_in[12];
    float* out = (float*)d_out;

    k_pre<<<1, 256>>>();
    k_node<<<NODE_BLKS + DEG_BLKS, 256>>>(x, ei, ea, W_lin, W_res, bias,
                                          w_s, b_s, w_t, b_t, W_edge, w_e, out);
    k_scan<<<SCB, 256>>>();
    k_scatter<<<(EE / 8 + 255) / 256, 256>>>(ei, b_e);
    k_aggr<<<(NN * 32) / 256, 256>>>(out);
}

// round 13
// speedup vs baseline: 1.1055x; 1.0941x over previous
#include <cuda_runtime.h>
#include <cuda_fp16.h>

#define NN 50000
#define EE 1600000
#define SCB 196          // ceil(NN/256) scan blocks
#define NODE_BLKS 600
#define DEG_BLKS  1024

// ---- scratch ----
__device__ uint2  g_xp2[NN * 32];        // node projections fp16 [N,128]
__device__ float  g_as[NN * 4];
__device__ float  g_at[NN * 4];
__device__ uint2  g_aeh[EE];             // per-edge a_e, 4 halfs
__device__ uint4  g_rec[EE];             // CSR: {w01h2, w23h2, src, pad}
__device__ int    g_deg[NN];             // zero-init first run; re-zeroed by k_scan
__device__ int    g_off[NN + 1];
__device__ int    g_cur[NN];
__device__ int    g_agg[SCB];
__device__ int    g_flag[SCB];           // zeroed by k_node edge block each run

__device__ __forceinline__ unsigned long long pack2f(float a, float b) {
    unsigned long long r;
    asm("mov.b64 %0, {%1, %2};" : "=l"(r) : "f"(a), "f"(b));
    return r;
}
__device__ __forceinline__ void unpack2f(unsigned long long v, float& a, float& b) {
    asm("mov.b64 {%0, %1}, %2;" : "=f"(a), "=f"(b) : "l"(v));
}
__device__ __forceinline__ unsigned long long fma2f(unsigned long long a,
                                                    unsigned long long b,
                                                    unsigned long long c) {
    unsigned long long r;
    asm("fma.rn.f32x2 %0, %1, %2, %3;" : "=l"(r) : "l"(a), "l"(b), "l"(c));
    return r;
}

// ---------------------------------------------------------------
// K1: FUSED (r10 structure). blocks < NODE_BLKS: persistent GEMM.
//     Remaining blocks: edge pass (flag zeroing, fire-and-forget degree
//     histogram + a_e dot -> fp16).
__global__ __launch_bounds__(256) void k_node(
    const float* __restrict__ x, const int* __restrict__ ei,
    const float* __restrict__ ea,
    const float* __restrict__ W_lin, const float* __restrict__ W_res,
    const float* __restrict__ bias,
    const float* __restrict__ w_s, const float* __restrict__ b_s,
    const float* __restrict__ w_t, const float* __restrict__ b_t,
    const float* __restrict__ W_edge, const float* __restrict__ w_e,
    float* __restrict__ out) {
    int t = threadIdx.x;
    if (blockIdx.x >= NODE_BLKS) {
        // ---- edge pass ----
        if (blockIdx.x == NODE_BLKS && t < SCB) g_flag[t] = 0;  // scan flags
        __shared__ float sve[64];
        if (t < 64) {
            int h = t >> 4, k = t & 15;
            float s = 0.f;
#pragma unroll
            for (int f = 0; f < 32; f++) s += w_e[f] * W_edge[(h * 32 + f) * 16 + k];
            sve[t] = s;
        }
        __syncthreads();
        int nb = gridDim.x - NODE_BLKS;
        for (int e = (blockIdx.x - NODE_BLKS) * 256 + t; e < EE;
             e += nb * 256) {
            int dst = ei[EE + e];
            atomicAdd(&g_deg[dst], 1);        // result unused -> REDG
            const float4* p = (const float4*)ea + e * 4;
            float av[16];
#pragma unroll
            for (int i = 0; i < 4; i++) {
                float4 q = p[i];
                av[4 * i] = q.x; av[4 * i + 1] = q.y;
                av[4 * i + 2] = q.z; av[4 * i + 3] = q.w;
            }
            float r[4];
#pragma unroll
            for (int h = 0; h < 4; h++) {
                const float* vv = sve + h * 16;
                float s = 0.f;
#pragma unroll
                for (int k = 0; k < 16; k++) s += vv[k] * av[k];
                r[h] = s;
            }
            half2 r01 = __floats2half2_rn(r[0], r[1]);
            half2 r23 = __floats2half2_rn(r[2], r[3]);
            uint2 u;
            u.x = *(unsigned*)&r01;
            u.y = *(unsigned*)&r23;
            g_aeh[e] = u;
        }
        return;
    }
    // ---- GEMM path ----
    __shared__ float sx[16 * 64];
    __shared__ float sxp[16 * 132];
    __shared__ float sws[32], swt[32];

    unsigned long long w2[32];
    {
        const float4* Wrow = (t < 128) ? ((const float4*)W_lin + t * 16)
                                       : ((const float4*)W_res + (t - 128) * 16);
#pragma unroll
        for (int k = 0; k < 16; k++) {
            float4 v = Wrow[k];
            w2[2 * k]     = pack2f(v.x, v.y);
            w2[2 * k + 1] = pack2f(v.z, v.w);
        }
    }
    float bval = (t >= 128) ? bias[t - 128] : 0.f;
    if (t < 32) sws[t] = w_s[t];
    else if (t < 64) swt[t - 32] = w_t[t - 32];
    float bsv = b_s[0], btv = b_t[0];
    int th = t >> 5, tf = t & 31;

    for (int tile = blockIdx.x; tile < NN / 16; tile += NODE_BLKS) {
        int n0 = tile * 16;
        __syncthreads();
        ((float4*)sx)[(t >> 4) * 16 + (t & 15)] =
            ((const float4*)x)[(n0 + (t >> 4)) * 16 + (t & 15)];
        __syncthreads();
#pragma unroll 1
        for (int i = 0; i < 16; i++) {
            const ulonglong2* xr = (const ulonglong2*)(sx + i * 64);
            unsigned long long a0 = 0ull, a1 = 0ull;
#pragma unroll
            for (int k = 0; k < 16; k++) {
                ulonglong2 xv = xr[k];
                a0 = fma2f(w2[2 * k],     xv.x, a0);
                a1 = fma2f(w2[2 * k + 1], xv.y, a1);
            }
            float l0, h0, l1, h1;
            unpack2f(a0, l0, h0);
            unpack2f(a1, l1, h1);
            float acc = (l0 + l1) + (h0 + h1);
            if (t < 128) {
                sxp[i * 132 + th * 33 + tf] = acc;
                ((__half*)g_xp2)[(n0 + i) * 128 + t] = __float2half(acc);
            } else {
                out[(n0 + i) * 128 + (t - 128)] = acc + bval;
            }
        }
        __syncthreads();
        if (t < 128) {
            int i = t >> 3, task = t & 7, h = task & 3;
            const float* wv  = (task < 4) ? sws : swt;
            const float* xpr = sxp + i * 132 + h * 33;
            float s = 0.f;
#pragma unroll
            for (int f = 0; f < 32; f++) s += xpr[f] * wv[f];
            if (task < 4) g_as[(n0 + i) * 4 + h] = s + bsv;
            else          g_at[(n0 + i) * 4 + h] = s + btv;
        }
    }
}

// ---------------------------------------------------------------
// K2: single-launch decoupled scan (196 co-resident blocks).
__global__ __launch_bounds__(256) void k_scan() {
    __shared__ int swsum[8];
    __shared__ int sbase[8];
    int t = threadIdx.x, lane = t & 31, w = t >> 5;
    int idx = blockIdx.x * 256 + t;
    int d = (idx < NN) ? g_deg[idx] : 0;

    int v = d;
#pragma unroll
    for (int o = 1; o < 32; o <<= 1) {
        int u = __shfl_up_sync(0xffffffffu, v, o);
        if (lane >= o) v += u;
    }
    if (lane == 31) swsum[w] = v;
    __syncthreads();
    if (w == 0) {
        int ws = (lane < 8) ? swsum[lane] : 0;
#pragma unroll
        for (int o = 1; o < 8; o <<= 1) {
            int u = __shfl_up_sync(0xffffffffu, ws, o);
            if (lane >= o) ws += u;
        }
        if (lane < 8) swsum[lane] = ws;
    }
    __syncthreads();
    int incl = v + (w > 0 ? swsum[w - 1] : 0);
    int total = swsum[7];

    if (t == 0) {
        g_agg[blockIdx.x] = total;
        __threadfence();
        g_flag[blockIdx.x] = 1;
    }

    int pre = 0;
    if (t < blockIdx.x) {
        while (((volatile int*)g_flag)[t] == 0) {}
        pre = ((volatile int*)g_agg)[t];
    }
#pragma unroll
    for (int o = 16; o > 0; o >>= 1) pre += __shfl_down_sync(0xffffffffu, pre, o);
    if (lane == 0) sbase[w] = pre;
    __syncthreads();
    if (t == 0) {
        int b = 0;
#pragma unroll
        for (int i = 0; i < 8; i++) b += sbase[i];
        sbase[0] = b;
    }
    __syncthreads();
    int base = sbase[0];

    if (idx < NN) {
        int off = base + incl - d;
        g_off[idx] = off;
        g_cur[idx] = off;
        g_deg[idx] = 0;
        if (idx == NN - 1) g_off[NN] = off + d;
    }
}

// ---------------------------------------------------------------
// K3: LEAN scatter — FOUR coalesced streams/thread (was 8: regs 86 ->
//     occ 21.6%, reg-capped at 2 blocks/SM). 4 streams ≈ 50 regs ->
//     ~5 blocks/SM, 2.5x warps in flight for the same latency-bound work.
__global__ __launch_bounds__(256) void k_scatter(
    const int* __restrict__ ei, const float* __restrict__ b_e) {
    const int QU = EE / 4;
    int gid = blockIdx.x * blockDim.x + threadIdx.x;
    if (gid >= QU) return;
    float bev = b_e[0];

    int   e[4], src[4], dst[4];
    uint2 ae[4];
    float4 as4[4], at4[4];
#pragma unroll
    for (int k = 0; k < 4; k++) e[k] = gid + k * QU;
#pragma unroll
    for (int k = 0; k < 4; k++) { src[k] = ei[e[k]]; dst[k] = ei[EE + e[k]]; }
#pragma unroll
    for (int k = 0; k < 4; k++) ae[k] = g_aeh[e[k]];
#pragma unroll
    for (int k = 0; k < 4; k++) {
        as4[k] = ((const float4*)g_as)[src[k]];
        at4[k] = ((const float4*)g_at)[dst[k]];
    }
#pragma unroll
    for (int k = 0; k < 4; k++) {
        float2 a01 = __half22float2(*(half2*)&ae[k].x);
        float2 a23 = __half22float2(*(half2*)&ae[k].y);
        float al[4];
        al[0] = a01.x + as4[k].x + at4[k].x + bev;
        al[1] = a01.y + as4[k].y + at4[k].y + bev;
        al[2] = a23.x + as4[k].z + at4[k].z + bev;
        al[3] = a23.y + as4[k].w + at4[k].w + bev;
        float w[4];
#pragma unroll
        for (int h = 0; h < 4; h++) {
            float s = (al[h] >= 0.f) ? al[h] : 0.2f * al[h];
            w[h] = __expf(s);
        }
        int pos = atomicAdd(&g_cur[dst[k]], 1);
        half2 w01 = __floats2half2_rn(w[0], w[1]);
        half2 w23 = __floats2half2_rn(w[2], w[3]);
        uint4 rec;
        rec.x = *(unsigned*)&w01;
        rec.y = *(unsigned*)&w23;
        rec.z = (unsigned)src[k];
        rec.w = 0u;
        g_rec[pos] = rec;
    }
}

// ---------------------------------------------------------------
// K4: EDGE-PAIRED aggregation, batch-8 (unchanged; profiled slot #4).
__device__ __forceinline__ void aggr_step(float* acc, float& sw,
                                          const uint4& r, const uint4& xv,
                                          int head) {
    unsigned wp = (head & 2) ? r.y : r.x;
    half2 hw = *(half2*)&wp;
    float w = (head & 1) ? __high2float(hw) : __low2float(hw);
    sw += w;
    float2 f0 = __half22float2(*(const half2*)&xv.x);
    float2 f1 = __half22float2(*(const half2*)&xv.y);
    float2 f2 = __half22float2(*(const half2*)&xv.z);
    float2 f3 = __half22float2(*(const half2*)&xv.w);
    acc[0] += w * f0.x; acc[1] += w * f0.y;
    acc[2] += w * f1.x; acc[3] += w * f1.y;
    acc[4] += w * f2.x; acc[5] += w * f2.y;
    acc[6] += w * f3.x; acc[7] += w * f3.y;
}

__global__ __launch_bounds__(256) void k_aggr(float* __restrict__ out) {
    int wid = (blockIdx.x * blockDim.x + threadIdx.x) >> 5;
    if (wid >= NN) return;
    int lane = threadIdx.x & 31;
    int half = lane >> 4;
    int sub  = lane & 15;
    int head = sub >> 2;
    int beg = g_off[wid], end = g_off[wid + 1];
    const uint4* xp4 = (const uint4*)g_xp2;

    float acc[8];
#pragma unroll
    for (int i = 0; i < 8; i++) acc[i] = 0.f;
    float sw = 0.f;

    int p = beg;
    for (; p + 8 <= end; p += 8) {
        uint4 r[4], xv[4];
#pragma unroll
        for (int j = 0; j < 4; j++) r[j] = g_rec[p + 2 * j + half];
#pragma unroll
        for (int j = 0; j < 4; j++) xv[j] = xp4[r[j].z * 16 + sub];
#pragma unroll
        for (int j = 0; j < 4; j++) aggr_step(acc, sw, r[j], xv[j], head);
    }
    for (; p + 2 <= end; p += 2) {
        uint4 r = g_rec[p + half];
        uint4 xv = xp4[r.z * 16 + sub];
        aggr_step(acc, sw, r, xv, head);
    }
    if (p < end) {
        uint4 r = g_rec[p];
        uint4 xv = xp4[r.z * 16 + sub];
        unsigned wp = (head & 2) ? r.y : r.x;
        half2 hw = *(half2*)&wp;
        float w = (head & 1) ? __high2float(hw) : __low2float(hw);
        if (half) w = 0.f;
        sw += w;
        float2 f0 = __half22float2(*(const half2*)&xv.x);
        float2 f1 = __half22float2(*(const half2*)&xv.y);
        float2 f2 = __half22float2(*(const half2*)&xv.z);
        float2 f3 = __half22float2(*(const half2*)&xv.w);
        acc[0] += w * f0.x; acc[1] += w * f0.y;
        acc[2] += w * f1.x; acc[3] += w * f1.y;
        acc[4] += w * f2.x; acc[5] += w * f2.y;
        acc[6] += w * f3.x; acc[7] += w * f3.y;
    }

    sw += __shfl_xor_sync(0xffffffffu, sw, 16);
#pragma unroll
    for (int i = 0; i < 8; i++)
        acc[i] += __shfl_xor_sync(0xffffffffu, acc[i], 16);

    float inv = (sw > 0.f) ? (1.f / sw) : 0.f;
    float4* o4 = (float4*)(out + wid * 128 + sub * 8 + half * 4);
    float4 ov = *o4;
    int b = half * 4;
    ov.x += inv * acc[b + 0]; ov.y += inv * acc[b + 1];
    ov.z += inv * acc[b + 2]; ov.w += inv * acc[b + 3];
    *o4 = ov;
}

// ---------------------------------------------------------------
extern "C" void kernel_launch(void* const* d_in, const int* in_sizes, int n_in,
                              void* d_out, int out_size) {
    const float* x      = (const float*)d_in[0];
    const int*   ei     = (const int*)  d_in[1];
    const float* ea     = (const float*)d_in[2];
    const float* W_lin  = (const float*)d_in[3];
    const float* w_s    = (const float*)d_in[4];
    const float* b_s    = (const float*)d_in[5];
    const float* w_t    = (const float*)d_in[6];
    const float* b_t    = (const float*)d_in[7];
    const float* W_edge = (const float*)d_in[8];
    const float* w_e    = (const float*)d_in[9];
    const float* b_e    = (const float*)d_in[10];
    const float* W_res  = (const float*)d_in[11];
    const float* bias   = (const float*)d_in[12];
    float* out = (float*)d_out;

    k_node<<<NODE_BLKS + DEG_BLKS, 256>>>(x, ei, ea, W_lin, W_res, bias,
                                          w_s, b_s, w_t, b_t, W_edge, w_e, out);
    k_scan<<<SCB, 256>>>();
    k_scatter<<<(EE / 4 + 255) / 256, 256>>>(ei, b_e);
    k_aggr<<<(NN * 32) / 256, 256>>>(out);
}